// round 11
// baseline (speedup 1.0000x reference)
#include <cuda_runtime.h>
#include <cuda_fp16.h>
#include <float.h>
#include <stdint.h>

#define NCODES   4096
#define CDIM     64
#define NTOK     65536
#define HW       4096
#define M_TILE   128
#define N_CHUNK  128
#define NCHUNKS  32
#define THREADS  256
#define SCALE    64.0f

#define B_STRIDE 144      // 64 halves (128B) + 16B pad -> conflict-free ldmatrix
#define ESQ_TAIL 18432    // esq tail offset inside each BH buffer

// ---- smem byte offsets (per CTA total 112640 = 110KB -> 2 CTAs/SM) ----
#define OFF_AH     0        // 128*144 fp16 z-hi tile (reused as gather stage with OFF_AL)
#define OFF_AL     18432    // 128*144 fp16 z-lo tile
#define OFF_BH0    36864    // 18432 data + 512 esq tail
#define OFF_BL0    55808
#define OFF_BH1    74752
#define OFF_BL1    93696    // ends 112640
#define SMEM_TOTAL 112640
// overlays (valid after main loop, inside B region):
#define OFF_CANDV  36864    // 2*128 floats
#define OFF_CANDI  37888    // 2*128 ints
#define OFF_SIDX   38912    // 128 ints

__device__ float  g_esq[NCODES];             // scaled by 4096
__device__ __half g_embh[NCODES * CDIM];     // hi(e*64)
__device__ __half g_embl[NCODES * CDIM];     // lo(e*64)

__device__ __forceinline__ uint32_t smem_u32(const void* p) {
    uint32_t a;
    asm("{ .reg .u64 t; cvta.to.shared.u64 t, %1; cvt.u32.u64 %0, t; }" : "=r"(a) : "l"(p));
    return a;
}
__device__ __forceinline__ void cp16(uint32_t dst, const void* src) {
    asm volatile("cp.async.cg.shared.global [%0], [%1], 16;" :: "r"(dst), "l"(src));
}
__device__ __forceinline__ void cp_commit() { asm volatile("cp.async.commit_group;"); }
template <int N>
__device__ __forceinline__ void cp_wait() { asm volatile("cp.async.wait_group %0;" :: "n"(N)); }

__device__ __forceinline__ void mma16816(float* c, const uint32_t* a, uint32_t b0, uint32_t b1) {
    asm volatile(
        "mma.sync.aligned.m16n8k16.row.col.f32.f16.f16.f32 "
        "{%0,%1,%2,%3}, {%4,%5,%6,%7}, {%8,%9}, {%0,%1,%2,%3};"
        : "+f"(c[0]), "+f"(c[1]), "+f"(c[2]), "+f"(c[3])
        : "r"(a[0]), "r"(a[1]), "r"(a[2]), "r"(a[3]), "r"(b0), "r"(b1));
}
__device__ __forceinline__ void ldmx4(uint32_t& r0, uint32_t& r1, uint32_t& r2, uint32_t& r3,
                                      uint32_t a) {
    asm volatile("ldmatrix.sync.aligned.m8n8.x4.shared.b16 {%0,%1,%2,%3}, [%4];"
        : "=r"(r0), "=r"(r1), "=r"(r2), "=r"(r3) : "r"(a));
}
__device__ __forceinline__ uint32_t pack2h(float v0, float v1) {
    __half h0 = __float2half_rn(v0);
    __half h1 = __float2half_rn(v1);
    return (uint32_t)__half_as_ushort(h0) | ((uint32_t)__half_as_ushort(h1) << 16);
}

// prep: hi/lo fp16 codebook (scaled by 64) + scaled ||e||^2. one warp per code.
__global__ void prep_kernel(const float* __restrict__ emb) {
    int warp = (blockIdx.x * blockDim.x + threadIdx.x) >> 5;
    int lane = threadIdx.x & 31;
    if (warp >= NCODES) return;
    const float* row = emb + (size_t)warp * CDIM;
    float v0 = row[lane] * SCALE, v1 = row[lane + 32] * SCALE;
    __half h0 = __float2half_rn(v0), h1 = __float2half_rn(v1);
    g_embh[warp * CDIM + lane]      = h0;
    g_embh[warp * CDIM + lane + 32] = h1;
    g_embl[warp * CDIM + lane]      = __float2half_rn(v0 - __half2float(h0));
    g_embl[warp * CDIM + lane + 32] = __float2half_rn(v1 - __half2float(h1));
    float s = v0 * v0 + v1 * v1;   // scale^2 * ||e||^2
    #pragma unroll
    for (int off = 16; off; off >>= 1) s += __shfl_xor_sync(0xffffffffu, s, off);
    if (lane == 0) g_esq[warp] = s;
}

__global__ __launch_bounds__(THREADS, 2)
void vq_kernel(const float* __restrict__ z,
               const float* __restrict__ emb,
               float* __restrict__ out) {
    extern __shared__ char sm[];
    float* candv = (float*)(sm + OFF_CANDV);
    int*   candi = (int*)(sm + OFF_CANDI);
    int*   sidx  = (int*)(sm + OFF_SIDX);

    const uint32_t sb = smem_u32(sm);
    const int tid  = threadIdx.x;
    const int lane = tid & 31;
    const int wid  = tid >> 5;
    const int grp  = lane >> 2;     // 0..7
    const int tid4 = lane & 3;      // 0..3
    const int mg   = wid >> 1;      // 0..3 : token rows mg*32 .. +31
    const int nw   = wid & 1;       // 0..1 : code cols nw*64 .. +63 within chunk

    const int n0  = blockIdx.x * M_TILE;
    const int bb  = n0 >> 12;
    const int hw0 = n0 & (HW - 1);
    const float* zb = z + (size_t)bb * CDIM * HW + hw0;

    const uint32_t bh_off[2] = { OFF_BH0, OFF_BH1 };
    const uint32_t bl_off[2] = { OFF_BL0, OFF_BL1 };

    // ---- issue cp.async for chunk 0 (hi + lo + esq tail) ----
    {
        #pragma unroll
        for (int t = 0; t < 8; t++) {
            int item = tid + 256 * t;
            int mat  = item >> 10;              // 0: hi, 1: lo
            int row  = (item >> 3) & 127;
            int part = item & 7;
            const __half* src = (mat ? g_embl : g_embh) + row * 64 + part * 8;
            uint32_t dst = sb + (mat ? OFF_BL0 : OFF_BH0) + row * B_STRIDE + part * 16;
            cp16(dst, src);
        }
        if (tid < 32)
            cp16(sb + OFF_BH0 + ESQ_TAIL + tid * 16, g_esq + tid * 4);
        cp_commit();
    }

    // ---- stage z as fp16 hi/lo tiles (scaled): row = token, 2B per c ----
    #pragma unroll
    for (int t = 0; t < 16; t++) {
        int i   = tid + 256 * t;           // 0..4095 over (c-pair, token)
        int c2  = (i >> 7) * 2;
        int tok = i & 127;
        float v0 = zb[(size_t)c2 * HW + tok] * SCALE;
        float v1 = zb[(size_t)(c2 + 1) * HW + tok] * SCALE;
        __half h0 = __float2half_rn(v0), h1 = __float2half_rn(v1);
        uint32_t hi = (uint32_t)__half_as_ushort(h0) | ((uint32_t)__half_as_ushort(h1) << 16);
        uint32_t lo = pack2h(v0 - __half2float(h0), v1 - __half2float(h1));
        *(uint32_t*)(sm + OFF_AH + tok * B_STRIDE + c2 * 2) = hi;
        *(uint32_t*)(sm + OFF_AL + tok * B_STRIDE + c2 * 2) = lo;
    }
    __syncthreads();

    // ldmatrix lane address pieces
    const int arow  = (lane & 7) + ((lane >> 3) & 1) * 8;   // A operand pattern
    const int akoff = ((lane >> 4) & 1) * 16;
    const int brow  = (lane & 7) + ((lane >> 4) & 1) * 8;   // B operand pattern
    const int bkoff = ((lane >> 3) & 1) * 16;

    // A-lo frag addresses for the warp's two m16 tiles
    const uint32_t alad0 = sb + OFF_AL + (uint32_t)(mg * 32 + arow) * B_STRIDE + akoff;
    const uint32_t alad1 = alad0 + 16 * B_STRIDE;

    // ---- Ah fragments in registers (loaded once via ldmatrix) ----
    uint32_t Ah[2][4][4];
    {
        const uint32_t ahad0 = sb + OFF_AH + (uint32_t)(mg * 32 + arow) * B_STRIDE + akoff;
        #pragma unroll
        for (int s = 0; s < 4; s++) {
            ldmx4(Ah[0][s][0], Ah[0][s][1], Ah[0][s][2], Ah[0][s][3], ahad0 + s * 32);
            ldmx4(Ah[1][s][0], Ah[1][s][1], Ah[1][s][2], Ah[1][s][3],
                  ahad0 + 16 * B_STRIDE + s * 32);
        }
    }
    cp_wait<0>();
    __syncthreads();

    float best[4];
    int   bidx[4];
    #pragma unroll
    for (int g = 0; g < 4; g++) { best[g] = FLT_MAX; bidx[g] = 0; }

    for (int ch = 0; ch < NCHUNKS; ch++) {
        const int buf = ch & 1;

        // issue next chunk into buf^1
        if (ch < NCHUNKS - 1) {
            const size_t cbase = (size_t)(ch + 1) * N_CHUNK * CDIM;
            #pragma unroll
            for (int t = 0; t < 8; t++) {
                int item = tid + 256 * t;
                int mat  = item >> 10;
                int row  = (item >> 3) & 127;
                int part = item & 7;
                const __half* src = (mat ? g_embl : g_embh) + cbase + row * 64 + part * 8;
                uint32_t dst = sb + (mat ? bl_off[buf ^ 1] : bh_off[buf ^ 1]) + row * B_STRIDE + part * 16;
                cp16(dst, src);
            }
            if (tid < 32)
                cp16(sb + bh_off[buf ^ 1] + ESQ_TAIL + tid * 16,
                     g_esq + (ch + 1) * N_CHUNK + tid * 4);
            cp_commit();
        }

        const float* esq_t = (const float*)(sm + bh_off[buf] + ESQ_TAIL);

        // ---- two n32 steps over this warp's n64 half ----
        #pragma unroll
        for (int step = 0; step < 2; step++) {
            const int nbase = nw * 64 + step * 32;
            const uint32_t bhb = sb + bh_off[buf] + (uint32_t)(nbase + brow) * B_STRIDE + bkoff;
            const uint32_t blb = sb + bl_off[buf] + (uint32_t)(nbase + brow) * B_STRIDE + bkoff;

            float acc[2][4][4];
            #pragma unroll
            for (int m = 0; m < 2; m++)
                #pragma unroll
                for (int f = 0; f < 4; f++)
                    #pragma unroll
                    for (int r = 0; r < 4; r++) acc[m][f][r] = 0.f;

            #pragma unroll
            for (int s = 0; s < 4; s++) {
                uint32_t al0[4], al1[4];
                ldmx4(al0[0], al0[1], al0[2], al0[3], alad0 + s * 32);
                ldmx4(al1[0], al1[1], al1[2], al1[3], alad1 + s * 32);
                #pragma unroll
                for (int fp = 0; fp < 2; fp++) {
                    uint32_t h0, h1, h2, h3, L0, L1, L2, L3;
                    ldmx4(h0, h1, h2, h3, bhb + fp * (16 * B_STRIDE) + s * 32);
                    const int f0 = 2 * fp, f1 = 2 * fp + 1;
                    // hi * hi
                    mma16816(acc[0][f0], Ah[0][s], h0, h1);
                    mma16816(acc[0][f1], Ah[0][s], h2, h3);
                    mma16816(acc[1][f0], Ah[1][s], h0, h1);
                    mma16816(acc[1][f1], Ah[1][s], h2, h3);
                    // lo * hi
                    mma16816(acc[0][f0], al0, h0, h1);
                    mma16816(acc[0][f1], al0, h2, h3);
                    mma16816(acc[1][f0], al1, h0, h1);
                    mma16816(acc[1][f1], al1, h2, h3);
                    // hi * lo
                    ldmx4(L0, L1, L2, L3, blb + fp * (16 * B_STRIDE) + s * 32);
                    mma16816(acc[0][f0], Ah[0][s], L0, L1);
                    mma16816(acc[0][f1], Ah[0][s], L2, L3);
                    mma16816(acc[1][f0], Ah[1][s], L0, L1);
                    mma16816(acc[1][f1], Ah[1][s], L2, L3);
                }
            }

            // ---- epilogue: min-tree + rare rescan (exact, first-min tiebreak) ----
            const int cb = ch * N_CHUNK + nbase;
            float2 ee[4];
            #pragma unroll
            for (int f = 0; f < 4; f++)
                ee[f] = *(const float2*)&esq_t[nbase + f * 8 + 2 * tid4];

            #pragma unroll
            for (int g = 0; g < 4; g++) {   // g = m*2+h : token mg*32 + m*16 + h*8 + grp
                const int m = g >> 1, h = g & 1;
                float sv[8];
                #pragma unroll
                for (int f = 0; f < 4; f++) {
                    sv[2 * f]     = fmaf(acc[m][f][h * 2 + 0], -2.0f, ee[f].x);
                    sv[2 * f + 1] = fmaf(acc[m][f][h * 2 + 1], -2.0f, ee[f].y);
                }
                float m01 = fminf(sv[0], sv[1]), m23 = fminf(sv[2], sv[3]);
                float m45 = fminf(sv[4], sv[5]), m67 = fminf(sv[6], sv[7]);
                float mn = fminf(fminf(m01, m23), fminf(m45, m67));
                if (mn < best[g]) {
                    best[g] = mn;
                    int found = -1;
                    #pragma unroll
                    for (int j = 0; j < 8; j++)
                        if (found < 0 && sv[j] == mn)
                            found = cb + (j >> 1) * 8 + 2 * tid4 + (j & 1);
                    bidx[g] = found;
                }
            }
        }

        cp_wait<0>();
        __syncthreads();
    }

    // ---- reduce over tid4 quad (codes), merge nw halves via smem ----
    #pragma unroll
    for (int g = 0; g < 4; g++) {
        float v  = best[g];
        int   id = bidx[g];
        #pragma unroll
        for (int off = 1; off <= 2; off <<= 1) {
            float ov = __shfl_xor_sync(0xffffffffu, v, off);
            int   oi = __shfl_xor_sync(0xffffffffu, id, off);
            if (ov < v || (ov == v && oi < id)) { v = ov; id = oi; }
        }
        if (tid4 == 0) {
            int token = mg * 32 + (g >> 1) * 16 + (g & 1) * 8 + grp;
            candv[nw * 128 + token] = v;
            candi[nw * 128 + token] = id;
        }
    }
    __syncthreads();
    if (tid < 128) {
        float v0 = candv[tid], v1 = candv[128 + tid];
        int   i0 = candi[tid], i1 = candi[128 + tid];
        sidx[tid] = (v1 < v0 || (v1 == v0 && i1 < i0)) ? i1 : i0;
    }
    __syncthreads();

    // ---- gather emb[idx], transposed coalesced write (stage over A tiles) ----
    float* st = (float*)(sm + OFF_AH);   // [128][65] = 33280 B < 36864 B
    #pragma unroll
    for (int t = 0; t < 32; t++) {
        int i = tid + 256 * t;
        int tok = i >> 6, c = i & 63;
        st[tok * 65 + c] = emb[(size_t)sidx[tok] * CDIM + c];
    }
    __syncthreads();
    float* ob = out + (size_t)bb * CDIM * HW + hw0;
    #pragma unroll
    for (int t = 0; t < 32; t++) {
        int i = tid + 256 * t;
        int c = i >> 7, tok = i & 127;
        ob[(size_t)c * HW + tok] = st[tok * 65 + c];
    }
}

extern "C" void kernel_launch(void* const* d_in, const int* in_sizes, int n_in,
                              void* d_out, int out_size) {
    const float* z   = (const float*)d_in[0];
    const float* emb = (const float*)d_in[1];
    float* out = (float*)d_out;

    cudaFuncSetAttribute(vq_kernel, cudaFuncAttributeMaxDynamicSharedMemorySize, SMEM_TOTAL);

    prep_kernel<<<NCODES / 8, 256>>>(emb);
    vq_kernel<<<NTOK / M_TILE, THREADS, SMEM_TOTAL>>>(z, emb, out);
}